// round 13
// baseline (speedup 1.0000x reference)
#include <cuda_runtime.h>
#include <cuda_bf16.h>
#include <cstddef>
#include <cstdint>

#define D 128
#define NODES_CAP 100000
#define EDGES_CAP 1600000
#define SCAN_B 1024

// ---------------- scratch (__device__ globals; no allocation) ---------------
__device__ int   g_counts[NODES_CAP];
__device__ int   g_offs  [NODES_CAP];
__device__ int   g_bsum  [128];
__device__ int4  g_swe   [EDGES_CAP];              // (src, ew bits, edge id, 0) sorted by dst
__device__ __nv_bfloat16 g_wh[128 * 256];                // Wcat hi   [o][k]
__device__ __nv_bfloat16 g_wm[128 * 256];                // Wcat mid  [o][k]

// ---------------------------------------------------------------------------
// prep: zero counts + weight split in one launch
// ---------------------------------------------------------------------------
__global__ __launch_bounds__(256) void prep_kernel(
    const float* __restrict__ Wn, const float* __restrict__ We,
    int n_nodes, int zblocks)
{
    if ((int)blockIdx.x < zblocks) {
        int i = blockIdx.x * 256 + threadIdx.x;
        if (i < n_nodes) g_counts[i] = 0;
    } else {
        int i = (blockIdx.x - zblocks) * 256 + threadIdx.x;
        if (i < 128 * 256) {
            int o = i >> 8, k = i & 255;
            float w = (k < 128) ? Wn[o * 128 + k] : We[o * 128 + (k - 128)];
            __nv_bfloat16 h = __float2bfloat16(w);
            g_wh[i] = h;
            g_wm[i] = __float2bfloat16(w - __bfloat162float(h));
        }
    }
}

__global__ __launch_bounds__(256) void hist_kernel(const int* __restrict__ dst, int E)
{
    int e = blockIdx.x * 256 + threadIdx.x;
    if (e < E) atomicAdd(&g_counts[dst[e]], 1);
}

// per-1024-block exclusive scan; g_bsum[b] = block total
__global__ __launch_bounds__(SCAN_B) void scan1(int n)
{
    __shared__ int wsum[32];
    int i = blockIdx.x * SCAN_B + threadIdx.x;
    int v = (i < n) ? g_counts[i] : 0;
    int x = v;
    #pragma unroll
    for (int d = 1; d < 32; d <<= 1) {
        int y = __shfl_up_sync(0xffffffffu, x, d);
        if ((threadIdx.x & 31) >= d) x += y;
    }
    if ((threadIdx.x & 31) == 31) wsum[threadIdx.x >> 5] = x;
    __syncthreads();
    if (threadIdx.x < 32) {
        int y = wsum[threadIdx.x];
        #pragma unroll
        for (int d = 1; d < 32; d <<= 1) {
            int z = __shfl_up_sync(0xffffffffu, y, d);
            if (threadIdx.x >= d) y += z;
        }
        wsum[threadIdx.x] = y;
    }
    __syncthreads();
    int base = (threadIdx.x >= 32) ? wsum[(threadIdx.x >> 5) - 1] : 0;
    int incl = base + x;
    if (i < n) g_offs[i] = incl - v;
    if (threadIdx.x == SCAN_B - 1) g_bsum[blockIdx.x] = incl;
}

// apply cross-block base: each block sums g_bsum[0..bid) itself (<=98 ints)
__global__ __launch_bounds__(SCAN_B) void scan_apply(int n)
{
    __shared__ int sbase;
    if (threadIdx.x < 32) {
        int acc = 0;
        for (int j = threadIdx.x; j < (int)blockIdx.x; j += 32) acc += g_bsum[j];
        #pragma unroll
        for (int d = 16; d > 0; d >>= 1) acc += __shfl_down_sync(0xffffffffu, acc, d);
        if (threadIdx.x == 0) sbase = acc;
    }
    __syncthreads();
    int i = blockIdx.x * SCAN_B + threadIdx.x;
    if (i < n) g_offs[i] += sbase;
}

__global__ __launch_bounds__(256) void scatter_ids(
    const int* __restrict__ dst, const int* __restrict__ src,
    const float* __restrict__ ew, int E)
{
    int e = blockIdx.x * 256 + threadIdx.x;
    if (e < E) {
        int p = atomicAdd(&g_offs[dst[e]], 1);
        g_swe[p] = make_int4(src[e], __float_as_int(ew[e]), e, 0);
    }
}

// ---------------------------------------------------------------------------
// bf16 split helpers
// ---------------------------------------------------------------------------
__device__ __forceinline__ uint2 pack4_hi(float4 v, float4* resid)
{
    __nv_bfloat162 p0 = __floats2bfloat162_rn(v.x, v.y);
    __nv_bfloat162 p1 = __floats2bfloat162_rn(v.z, v.w);
    resid->x = v.x - __bfloat162float(__low2bfloat16(p0));
    resid->y = v.y - __bfloat162float(__high2bfloat16(p0));
    resid->z = v.z - __bfloat162float(__low2bfloat16(p1));
    resid->w = v.w - __bfloat162float(__high2bfloat16(p1));
    uint2 r;
    r.x = *reinterpret_cast<unsigned*>(&p0);
    r.y = *reinterpret_cast<unsigned*>(&p1);
    return r;
}
__device__ __forceinline__ uint2 pack4(float4 v)
{
    __nv_bfloat162 p0 = __floats2bfloat162_rn(v.x, v.y);
    __nv_bfloat162 p1 = __floats2bfloat162_rn(v.z, v.w);
    uint2 r;
    r.x = *reinterpret_cast<unsigned*>(&p0);
    r.y = *reinterpret_cast<unsigned*>(&p1);
    return r;
}

// ---------------------------------------------------------------------------
// FUSED aggregate + HMMA GEMM.
// Phase 1: 16 warps aggregate 128 nodes (8/warp), write normalized bf16
//          hi/mid planes directly into chunked pitch-40 smem (GEMM layout).
// Phase 2: 16 warps (4Mx4N) mma.sync GEMM; W streamed via cp.async 2-stage.
// smem: A planes 2x8x128x40 bf16 = 160KB ; W 2 bufs x 2 planes x128x40 = 40KB.
// ---------------------------------------------------------------------------
#define LDMX4(r0, r1, r2, r3, addr)                                                \
    asm volatile("ldmatrix.sync.aligned.m8n8.x4.shared.b16 {%0,%1,%2,%3}, [%4];"   \
                 : "=r"(r0), "=r"(r1), "=r"(r2), "=r"(r3) : "r"(addr))

#define MMA16816(d, a, b0, b1)                                                     \
    asm volatile("mma.sync.aligned.m16n8k16.row.col.f32.bf16.bf16.f32 "            \
                 "{%0,%1,%2,%3},{%4,%5,%6,%7},{%8,%9},{%0,%1,%2,%3};"              \
                 : "+f"((d)[0]), "+f"((d)[1]), "+f"((d)[2]), "+f"((d)[3])          \
                 : "r"((a)[0]), "r"((a)[1]), "r"((a)[2]), "r"((a)[3]),             \
                   "r"(b0), "r"(b1))

#define CP16(dst, src)                                                             \
    asm volatile("cp.async.cg.shared.global [%0], [%1], 16;" :: "r"(dst), "l"(src))
#define CP_COMMIT() asm volatile("cp.async.commit_group;" ::: "memory")
#define CP_WAIT1()  asm volatile("cp.async.wait_group 1;" ::: "memory")
#define CP_WAIT0()  asm volatile("cp.async.wait_group 0;" ::: "memory")

#define FPITCH 40
#define A_ELEMS (2 * 8 * 128 * FPITCH)     // 81920 bf16 elems (163840 B)
#define W_BUF_ELEMS (2 * 128 * FPITCH)     // 10240 bf16 elems per buffer
#define FSMEM_BYTES ((A_ELEMS + 2 * W_BUF_ELEMS) * 2)   // 204800 B

__global__ __launch_bounds__(512) void fused_kernel(
    const float* __restrict__ nfeat, const float* __restrict__ efeat,
    const float* __restrict__ bn, const float* __restrict__ be,
    float* __restrict__ out, int Nn)
{
    extern __shared__ __nv_bfloat16 smem[];
    const uint32_t smem_b = (uint32_t)__cvta_generic_to_shared(smem);

    const int tid  = threadIdx.x;
    const int wid  = tid >> 5;
    const int lane = tid & 31;
    const int mBase = blockIdx.x * 128;

    // ---- W chunk loader: 1024 x 16B units, 2 per thread ----
    auto issueW = [&](int kc, int b) {
        #pragma unroll
        for (int t = 0; t < 2; t++) {
            int u = tid * 2 + t;
            int p = u >> 9, rest = u & 511;
            int r = rest >> 2, q = rest & 3;
            const __nv_bfloat16* gsrc = (p ? g_wm : g_wh) + r * 256 + kc * 32 + q * 8;
            uint32_t dst = smem_b +
                (uint32_t)(A_ELEMS + b * W_BUF_ELEMS + (p * 128 + r) * FPITCH + q * 8) * 2;
            CP16(dst, gsrc);
        }
    };

    issueW(0, 0);
    CP_COMMIT();

    // ================= Phase 1: aggregate 8 nodes per warp =================
    {
        const float4* nf4 = reinterpret_cast<const float4*>(nfeat);
        const float4* ef4 = reinterpret_cast<const float4*>(efeat);
        const int c   = lane >> 3;          // k-chunk within 128 (0..3)
        const int col = (lane & 7) * 4;

        for (int j = 0; j < 8; j++) {
            int row = wid + 16 * j;         // 0..127
            int n = mBase + row;
            int nc = (n < Nn) ? n : (Nn - 1);

            int end = g_offs[nc];
            int cnt = g_counts[nc];
            int beg = end - cnt;

            float4 aN = make_float4(0.f, 0.f, 0.f, 0.f);
            float4 aE = make_float4(0.f, 0.f, 0.f, 0.f);

            int i = beg;
            for (; i + 4 <= end; i += 4) {
                int4 q0 = __ldcs(g_swe + i);
                int4 q1 = __ldcs(g_swe + i + 1);
                int4 q2 = __ldcs(g_swe + i + 2);
                int4 q3 = __ldcs(g_swe + i + 3);
                float4 a0 = __ldg(nf4 + (size_t)q0.x * 32 + lane);
                float4 a1 = __ldg(nf4 + (size_t)q1.x * 32 + lane);
                float4 a2 = __ldg(nf4 + (size_t)q2.x * 32 + lane);
                float4 a3 = __ldg(nf4 + (size_t)q3.x * 32 + lane);
                float4 v0 = __ldcs(ef4 + (size_t)q0.z * 32 + lane);
                float4 v1 = __ldcs(ef4 + (size_t)q1.z * 32 + lane);
                float4 v2 = __ldcs(ef4 + (size_t)q2.z * 32 + lane);
                float4 v3 = __ldcs(ef4 + (size_t)q3.z * 32 + lane);
                float w0 = __int_as_float(q0.y), w1 = __int_as_float(q1.y);
                float w2 = __int_as_float(q2.y), w3 = __int_as_float(q3.y);
                aN.x += a0.x * w0 + a1.x * w1 + a2.x * w2 + a3.x * w3;
                aN.y += a0.y * w0 + a1.y * w1 + a2.y * w2 + a3.y * w3;
                aN.z += a0.z * w0 + a1.z * w1 + a2.z * w2 + a3.z * w3;
                aN.w += a0.w * w0 + a1.w * w1 + a2.w * w2 + a3.w * w3;
                aE.x += (v0.x + v1.x) + (v2.x + v3.x);
                aE.y += (v0.y + v1.y) + (v2.y + v3.y);
                aE.z += (v0.z + v1.z) + (v2.z + v3.z);
                aE.w += (v0.w + v1.w) + (v2.w + v3.w);
            }
            for (; i < end; i++) {
                int4 q = __ldcs(g_swe + i);
                float w = __int_as_float(q.y);
                float4 a = __ldg(nf4 + (size_t)q.x * 32 + lane);
                float4 v = __ldcs(ef4 + (size_t)q.z * 32 + lane);
                aN.x += a.x * w;  aN.y += a.y * w;  aN.z += a.z * w;  aN.w += a.w * w;
                aE.x += v.x;  aE.y += v.y;  aE.z += v.z;  aE.w += v.w;
            }

            float invD = 1.f / ((float)cnt + 1.f);
            float invE = 1.f / (float)max(cnt, 1);
            float4 f = __ldg(nf4 + (size_t)nc * 32 + lane);

            float4 xn = make_float4((aN.x + 2.f * f.x) * invD, (aN.y + 2.f * f.y) * invD,
                                    (aN.z + 2.f * f.z) * invD, (aN.w + 2.f * f.w) * invD);
            float4 xe = make_float4(aE.x * invE, aE.y * invE, aE.z * invE, aE.w * invE);

            // write into chunked pitch-40 planes: plane p (0=hi,1=mid), chunk kc
            float4 r;
            uint2 h0 = pack4_hi(xn, &r);  uint2 m0 = pack4(r);
            uint2 h1 = pack4_hi(xe, &r);  uint2 m1 = pack4(r);
            int base_n = (c * 128 + row) * FPITCH + col;            // xn: chunks 0..3
            int base_e = ((c + 4) * 128 + row) * FPITCH + col;      // xe: chunks 4..7
            *reinterpret_cast<uint2*>(smem + base_n)                       = h0;
            *reinterpret_cast<uint2*>(smem + (8 * 128 * FPITCH) + base_n)  = m0;
            *reinterpret_cast<uint2*>(smem + base_e)                       = h1;
            *reinterpret_cast<uint2*>(smem + (8 * 128 * FPITCH) + base_e)  = m1;
        }
    }
    __syncthreads();

    // ================= Phase 2: HMMA GEMM =================
    const int warpM = wid & 3;          // 4 x 32 rows
    const int warpN = wid >> 2;         // 4 x 32 cols

    float d[2][4][4];
    #pragma unroll
    for (int mt = 0; mt < 2; mt++)
        #pragma unroll
        for (int nt = 0; nt < 4; nt++)
            #pragma unroll
            for (int cc = 0; cc < 4; cc++) d[mt][nt][cc] = 0.f;

    const int rA = (lane & 7) + ((lane >> 3) & 1) * 8;
    const int cA = (lane >> 4) * 8;
    const int rB = (lane & 7) + ((lane >> 4) & 1) * 8;
    const int cB = ((lane >> 3) & 1) * 8;

    for (int kc = 0; kc < 8; kc++) {
        int b = kc & 1;
        if (kc < 7) {
            issueW(kc + 1, b ^ 1);
            CP_COMMIT();
            CP_WAIT1();
        } else {
            CP_WAIT0();
        }
        __syncthreads();

        uint32_t pAh = smem_b + (uint32_t)(kc * 128 * FPITCH) * 2;
        uint32_t pAm = smem_b + (uint32_t)((8 + kc) * 128 * FPITCH) * 2;
        uint32_t pWh = smem_b + (uint32_t)(A_ELEMS + b * W_BUF_ELEMS) * 2;
        uint32_t pWm = pWh + (uint32_t)(128 * FPITCH) * 2;

        #pragma unroll
        for (int kg = 0; kg < 2; kg++) {
            unsigned ah[2][4], am[2][4], bh[2][4], bm[2][4];
            #pragma unroll
            for (int mt = 0; mt < 2; mt++) {
                uint32_t a = pAh + (uint32_t)((warpM * 32 + mt * 16 + rA) * FPITCH
                                              + kg * 16 + cA) * 2;
                LDMX4(ah[mt][0], ah[mt][1], ah[mt][2], ah[mt][3], a);
            }
            #pragma unroll
            for (int ng = 0; ng < 2; ng++) {
                uint32_t a = pWh + (uint32_t)((warpN * 32 + ng * 16 + rB) * FPITCH
                                              + kg * 16 + cB) * 2;
                LDMX4(bh[ng][0], bh[ng][1], bh[ng][2], bh[ng][3], a);
            }
            #pragma unroll
            for (int mt = 0; mt < 2; mt++)
                #pragma unroll
                for (int ng = 0; ng < 2; ng++) {
                    MMA16816(d[mt][2 * ng],     ah[mt], bh[ng][0], bh[ng][1]);
                    MMA16816(d[mt][2 * ng + 1], ah[mt], bh[ng][2], bh[ng][3]);
                }
            #pragma unroll
            for (int ng = 0; ng < 2; ng++) {
                uint32_t a = pWm + (uint32_t)((warpN * 32 + ng * 16 + rB) * FPITCH
                                              + kg * 16 + cB) * 2;
                LDMX4(bm[ng][0], bm[ng][1], bm[ng][2], bm[ng][3], a);
            }
            #pragma unroll
            for (int mt = 0; mt < 2; mt++)
                #pragma unroll
                for (int ng = 0; ng < 2; ng++) {
                    MMA16816(d[mt][2 * ng],     ah[mt], bm[ng][0], bm[ng][1]);
                    MMA16816(d[mt][2 * ng + 1], ah[mt], bm[ng][2], bm[ng][3]);
                }
            #pragma unroll
            for (int mt = 0; mt < 2; mt++) {
                uint32_t a = pAm + (uint32_t)((warpM * 32 + mt * 16 + rA) * FPITCH
                                              + kg * 16 + cA) * 2;
                LDMX4(am[mt][0], am[mt][1], am[mt][2], am[mt][3], a);
            }
            #pragma unroll
            for (int mt = 0; mt < 2; mt++)
                #pragma unroll
                for (int ng = 0; ng < 2; ng++) {
                    MMA16816(d[mt][2 * ng],     am[mt], bh[ng][0], bh[ng][1]);
                    MMA16816(d[mt][2 * ng + 1], am[mt], bh[ng][2], bh[ng][3]);
                }
        }
        __syncthreads();
    }

    // epilogue
    const int l4 = lane >> 2;
    const int l2 = (lane & 3) * 2;
    #pragma unroll
    for (int mt = 0; mt < 2; mt++) {
        int m0 = mBase + warpM * 32 + mt * 16 + l4;
        int m1 = m0 + 8;
        bool v0 = (m0 < Nn), v1 = (m1 < Nn);
        float he0 = (v0 && g_counts[m0] > 0) ? 1.f : 0.f;
        float he1 = (v1 && g_counts[m1] > 0) ? 1.f : 0.f;
        #pragma unroll
        for (int nt = 0; nt < 4; nt++) {
            int col = warpN * 32 + nt * 8 + l2;
            float2 b2 = *reinterpret_cast<const float2*>(bn + col);
            float2 e2 = *reinterpret_cast<const float2*>(be + col);
            if (v0) {
                float2 o0 = make_float2(d[mt][nt][0] + b2.x + he0 * e2.x,
                                        d[mt][nt][1] + b2.y + he0 * e2.y);
                *reinterpret_cast<float2*>(out + (size_t)m0 * D + col) = o0;
            }
            if (v1) {
                float2 o1 = make_float2(d[mt][nt][2] + b2.x + he1 * e2.x,
                                        d[mt][nt][3] + b2.y + he1 * e2.y);
                *reinterpret_cast<float2*>(out + (size_t)m1 * D + col) = o1;
            }
        }
    }
}

// ---------------------------------------------------------------------------
extern "C" void kernel_launch(void* const* d_in, const int* in_sizes, int n_in,
                              void* d_out, int out_size)
{
    const float* nfeat = (const float*)d_in[0];
    const float* efeat = (const float*)d_in[1];
    const float* ew    = (const float*)d_in[2];
    const float* Wn    = (const float*)d_in[3];
    const float* bn    = (const float*)d_in[4];
    const float* We    = (const float*)d_in[5];
    const float* be    = (const float*)d_in[6];
    const int*   src   = (const int*)d_in[7];
    const int*   dst   = (const int*)d_in[8];
    float* out = (float*)d_out;

    int Nn = in_sizes[0] / D;     // 100000
    int E  = in_sizes[2];         // 1600000
    int nScanBlocks = (Nn + SCAN_B - 1) / SCAN_B;
    int zblocks = (Nn + 255) / 256;

    cudaFuncSetAttribute(fused_kernel, cudaFuncAttributeMaxDynamicSharedMemorySize,
                         FSMEM_BYTES);

    prep_kernel<<<zblocks + 128, 256>>>(Wn, We, Nn, zblocks);
    hist_kernel<<<(E + 255) / 256, 256>>>(dst, E);
    scan1<<<nScanBlocks, SCAN_B>>>(Nn);
    scan_apply<<<nScanBlocks, SCAN_B>>>(Nn);
    scatter_ids<<<(E + 255) / 256, 256>>>(dst, src, ew, E);
    fused_kernel<<<(Nn + 127) / 128, 512, FSMEM_BYTES>>>(nfeat, efeat, bn, be, out, Nn);
}

// round 14
// speedup vs baseline: 1.3691x; 1.3691x over previous
#include <cuda_runtime.h>
#include <cuda_bf16.h>
#include <cuda_fp16.h>
#include <cstddef>
#include <cstdint>

#define D 128
#define NODES_CAP 100000
#define EDGES_CAP 1600000
#define SCAN_B 1024

// ---------------- scratch (__device__ globals; no allocation) ---------------
__device__ int   g_counts[NODES_CAP];
__device__ int   g_offs  [NODES_CAP];
__device__ int   g_bsum  [128];
__device__ int4  g_swe   [EDGES_CAP];              // (src, ew bits, edge id, 0) sorted by dst
__device__ __half g_nf16[(size_t)NODES_CAP * 128]; // fp16 copy of nfeat (gather table)
// X rows: per node 512 bf16 = [hi plane 256 | mid plane 256], contiguous 1KB
__device__ __nv_bfloat16 g_x [(size_t)NODES_CAP * 512];
__device__ __nv_bfloat16 g_wh[128 * 256];                // Wcat hi   [o][k]
__device__ __nv_bfloat16 g_wm[128 * 256];                // Wcat mid  [o][k]

// ---------------------------------------------------------------------------
// prep: zero counts + weight split + nfeat->fp16 conversion, one launch
// ---------------------------------------------------------------------------
__global__ __launch_bounds__(256) void prep_kernel(
    const float* __restrict__ Wn, const float* __restrict__ We,
    const float* __restrict__ nfeat,
    int n_nodes, int zblocks, int cvblocks)
{
    int b = blockIdx.x;
    if (b < zblocks) {
        int i = b * 256 + threadIdx.x;
        if (i < n_nodes) g_counts[i] = 0;
    } else if (b < zblocks + 128) {
        int i = (b - zblocks) * 256 + threadIdx.x;
        if (i < 128 * 256) {
            int o = i >> 8, k = i & 255;
            float w = (k < 128) ? Wn[o * 128 + k] : We[o * 128 + (k - 128)];
            __nv_bfloat16 h = __float2bfloat16(w);
            g_wh[i] = h;
            g_wm[i] = __float2bfloat16(w - __bfloat162float(h));
        }
    } else {
        // convert 4 floats per thread to fp16
        size_t i = (size_t)(b - zblocks - 128) * 256 + threadIdx.x;
        size_t total4 = (size_t)n_nodes * 32;      // 128/4 per row
        if (i < total4) {
            float4 v = *(reinterpret_cast<const float4*>(nfeat) + i);
            __half2 h0 = __floats2half2_rn(v.x, v.y);
            __half2 h1 = __floats2half2_rn(v.z, v.w);
            uint2 p;
            p.x = *reinterpret_cast<unsigned*>(&h0);
            p.y = *reinterpret_cast<unsigned*>(&h1);
            reinterpret_cast<uint2*>(g_nf16)[i] = p;
        }
    }
}

__global__ __launch_bounds__(256) void hist_kernel(const int* __restrict__ dst, int E)
{
    int e = blockIdx.x * 256 + threadIdx.x;
    if (e < E) atomicAdd(&g_counts[dst[e]], 1);
}

// per-1024-block exclusive scan; g_bsum[b] = block total
__global__ __launch_bounds__(SCAN_B) void scan1(int n)
{
    __shared__ int wsum[32];
    int i = blockIdx.x * SCAN_B + threadIdx.x;
    int v = (i < n) ? g_counts[i] : 0;
    int x = v;
    #pragma unroll
    for (int d = 1; d < 32; d <<= 1) {
        int y = __shfl_up_sync(0xffffffffu, x, d);
        if ((threadIdx.x & 31) >= d) x += y;
    }
    if ((threadIdx.x & 31) == 31) wsum[threadIdx.x >> 5] = x;
    __syncthreads();
    if (threadIdx.x < 32) {
        int y = wsum[threadIdx.x];
        #pragma unroll
        for (int d = 1; d < 32; d <<= 1) {
            int z = __shfl_up_sync(0xffffffffu, y, d);
            if (threadIdx.x >= d) y += z;
        }
        wsum[threadIdx.x] = y;
    }
    __syncthreads();
    int base = (threadIdx.x >= 32) ? wsum[(threadIdx.x >> 5) - 1] : 0;
    int incl = base + x;
    if (i < n) g_offs[i] = incl - v;
    if (threadIdx.x == SCAN_B - 1) g_bsum[blockIdx.x] = incl;
}

// apply cross-block base: each block sums g_bsum[0..bid) itself (<=98 ints)
__global__ __launch_bounds__(SCAN_B) void scan_apply(int n)
{
    __shared__ int sbase;
    if (threadIdx.x < 32) {
        int acc = 0;
        for (int j = threadIdx.x; j < (int)blockIdx.x; j += 32) acc += g_bsum[j];
        #pragma unroll
        for (int d = 16; d > 0; d >>= 1) acc += __shfl_down_sync(0xffffffffu, acc, d);
        if (threadIdx.x == 0) sbase = acc;
    }
    __syncthreads();
    int i = blockIdx.x * SCAN_B + threadIdx.x;
    if (i < n) g_offs[i] += sbase;
}

__global__ __launch_bounds__(256) void scatter_ids(
    const int* __restrict__ dst, const int* __restrict__ src,
    const float* __restrict__ ew, int E)
{
    int e = blockIdx.x * 256 + threadIdx.x;
    if (e < E) {
        int p = atomicAdd(&g_offs[dst[e]], 1);
        g_swe[p] = make_int4(src[e], __float_as_int(ew[e]), e, 0);
    }
}

// ---------------------------------------------------------------------------
// bf16 split helpers
// ---------------------------------------------------------------------------
__device__ __forceinline__ uint2 pack4_hi(float4 v, float4* resid)
{
    __nv_bfloat162 p0 = __floats2bfloat162_rn(v.x, v.y);
    __nv_bfloat162 p1 = __floats2bfloat162_rn(v.z, v.w);
    resid->x = v.x - __bfloat162float(__low2bfloat16(p0));
    resid->y = v.y - __bfloat162float(__high2bfloat16(p0));
    resid->z = v.z - __bfloat162float(__low2bfloat16(p1));
    resid->w = v.w - __bfloat162float(__high2bfloat16(p1));
    uint2 r;
    r.x = *reinterpret_cast<unsigned*>(&p0);
    r.y = *reinterpret_cast<unsigned*>(&p1);
    return r;
}
__device__ __forceinline__ uint2 pack4(float4 v)
{
    __nv_bfloat162 p0 = __floats2bfloat162_rn(v.x, v.y);
    __nv_bfloat162 p1 = __floats2bfloat162_rn(v.z, v.w);
    uint2 r;
    r.x = *reinterpret_cast<unsigned*>(&p0);
    r.y = *reinterpret_cast<unsigned*>(&p1);
    return r;
}

// ---------------------------------------------------------------------------
// Warp-per-node aggregation; neighbor gather from fp16 table (half traffic).
// Writes normalized X row [hi|mid] (512 bf16, 1KB).
// ---------------------------------------------------------------------------
__device__ __forceinline__ float4 gather_h4(const uint2* row, int lane)
{
    uint2 p = __ldg(row + lane);
    __half2 h0 = *reinterpret_cast<__half2*>(&p.x);
    __half2 h1 = *reinterpret_cast<__half2*>(&p.y);
    float2 f0 = __half22float2(h0);
    float2 f1 = __half22float2(h1);
    return make_float4(f0.x, f0.y, f1.x, f1.y);
}

__global__ __launch_bounds__(256) void aggregate_kernel(
    const float* __restrict__ nfeat, const float* __restrict__ efeat, int Nn)
{
    int n = blockIdx.x * 8 + (threadIdx.x >> 5);
    if (n >= Nn) return;
    int lane = threadIdx.x & 31;

    int end = g_offs[n];
    int cnt = g_counts[n];
    int beg = end - cnt;

    const float4* nf4 = reinterpret_cast<const float4*>(nfeat);
    const float4* ef4 = reinterpret_cast<const float4*>(efeat);
    const uint2*  nh  = reinterpret_cast<const uint2*>(g_nf16);

    float4 aN = make_float4(0.f, 0.f, 0.f, 0.f);
    float4 aE = make_float4(0.f, 0.f, 0.f, 0.f);

    int i = beg;
    for (; i + 4 <= end; i += 4) {
        int4 q0 = __ldcs(g_swe + i);
        int4 q1 = __ldcs(g_swe + i + 1);
        int4 q2 = __ldcs(g_swe + i + 2);
        int4 q3 = __ldcs(g_swe + i + 3);
        float4 a0 = gather_h4(nh + (size_t)q0.x * 32, lane);
        float4 a1 = gather_h4(nh + (size_t)q1.x * 32, lane);
        float4 a2 = gather_h4(nh + (size_t)q2.x * 32, lane);
        float4 a3 = gather_h4(nh + (size_t)q3.x * 32, lane);
        float4 v0 = __ldcs(ef4 + (size_t)q0.z * 32 + lane);
        float4 v1 = __ldcs(ef4 + (size_t)q1.z * 32 + lane);
        float4 v2 = __ldcs(ef4 + (size_t)q2.z * 32 + lane);
        float4 v3 = __ldcs(ef4 + (size_t)q3.z * 32 + lane);
        float w0 = __int_as_float(q0.y), w1 = __int_as_float(q1.y);
        float w2 = __int_as_float(q2.y), w3 = __int_as_float(q3.y);
        aN.x += a0.x * w0 + a1.x * w1 + a2.x * w2 + a3.x * w3;
        aN.y += a0.y * w0 + a1.y * w1 + a2.y * w2 + a3.y * w3;
        aN.z += a0.z * w0 + a1.z * w1 + a2.z * w2 + a3.z * w3;
        aN.w += a0.w * w0 + a1.w * w1 + a2.w * w2 + a3.w * w3;
        aE.x += (v0.x + v1.x) + (v2.x + v3.x);
        aE.y += (v0.y + v1.y) + (v2.y + v3.y);
        aE.z += (v0.z + v1.z) + (v2.z + v3.z);
        aE.w += (v0.w + v1.w) + (v2.w + v3.w);
    }
    for (; i < end; i++) {
        int4 q = __ldcs(g_swe + i);
        float w = __int_as_float(q.y);
        float4 a = gather_h4(nh + (size_t)q.x * 32, lane);
        float4 v = __ldcs(ef4 + (size_t)q.z * 32 + lane);
        aN.x += a.x * w;  aN.y += a.y * w;  aN.z += a.z * w;  aN.w += a.w * w;
        aE.x += v.x;  aE.y += v.y;  aE.z += v.z;  aE.w += v.w;
    }

    float invD = 1.f / ((float)cnt + 1.f);
    float invE = 1.f / (float)max(cnt, 1);
    float4 f = __ldg(nf4 + (size_t)n * 32 + lane);   // self term stays fp32

    float4 xn = make_float4((aN.x + 2.f * f.x) * invD, (aN.y + 2.f * f.y) * invD,
                            (aN.z + 2.f * f.z) * invD, (aN.w + 2.f * f.w) * invD);
    float4 xe = make_float4(aE.x * invE, aE.y * invE, aE.z * invE, aE.w * invE);

    // row layout: [hi 256 | mid 256] bf16
    uint2* xr = reinterpret_cast<uint2*>(g_x + (size_t)n * 512);
    float4 r;
    xr[lane]      = pack4_hi(xn, &r);  xr[64 + lane] = pack4(r);
    xr[32 + lane] = pack4_hi(xe, &r);  xr[96 + lane] = pack4(r);
}

// ---------------------------------------------------------------------------
// HMMA GEMM, cp.async double-buffered.
// Block: 128(M) x 128(N), 8 warps (4Mx2N), warp tile 32x64, K in 8 chunks of 32.
// Smem pitch 40 bf16 -> conflict-free ldmatrix. 2-stage pipeline, 80KB dyn smem.
// ---------------------------------------------------------------------------
#define LDMX4(r0, r1, r2, r3, addr)                                                \
    asm volatile("ldmatrix.sync.aligned.m8n8.x4.shared.b16 {%0,%1,%2,%3}, [%4];"   \
                 : "=r"(r0), "=r"(r1), "=r"(r2), "=r"(r3) : "r"(addr))

#define MMA16816(d, a, b0, b1)                                                     \
    asm volatile("mma.sync.aligned.m16n8k16.row.col.f32.bf16.bf16.f32 "            \
                 "{%0,%1,%2,%3},{%4,%5,%6,%7},{%8,%9},{%0,%1,%2,%3};"              \
                 : "+f"((d)[0]), "+f"((d)[1]), "+f"((d)[2]), "+f"((d)[3])          \
                 : "r"((a)[0]), "r"((a)[1]), "r"((a)[2]), "r"((a)[3]),             \
                   "r"(b0), "r"(b1))

#define CP16(dst, src)                                                             \
    asm volatile("cp.async.cg.shared.global [%0], [%1], 16;" :: "r"(dst), "l"(src))
#define CP_COMMIT() asm volatile("cp.async.commit_group;" ::: "memory")
#define CP_WAIT1()  asm volatile("cp.async.wait_group 1;" ::: "memory")
#define CP_WAIT0()  asm volatile("cp.async.wait_group 0;" ::: "memory")

#define PITCH 40
#define PLANE_ELEMS (128 * PITCH)
#define PLANE_BYTES (PLANE_ELEMS * 2)
#define GSMEM_TOTAL (8 * PLANE_BYTES)     // 81920

__global__ __launch_bounds__(256) void gemm_mma(
    const float* __restrict__ bn, const float* __restrict__ be,
    float* __restrict__ out, int Nn)
{
    extern __shared__ __nv_bfloat16 smem[];
    const uint32_t smem_b = (uint32_t)__cvta_generic_to_shared(smem);

    const int tid  = threadIdx.x;
    const int wid  = tid >> 5;
    const int lane = tid & 31;
    const int warpM = wid & 3;
    const int warpN = wid >> 2;
    const int mBase = blockIdx.x * 128;

    float d[2][8][4];
    #pragma unroll
    for (int mt = 0; mt < 2; mt++)
        #pragma unroll
        for (int nt = 0; nt < 8; nt++)
            #pragma unroll
            for (int c = 0; c < 4; c++) d[mt][nt][c] = 0.f;

    // loaders: 2 threads per row, each 2 x 16B of the 64B k-chunk row
    const int lrow = tid >> 1;
    const int lt   = (tid & 1) * 2;
    int arow = mBase + lrow; if (arow >= Nn) arow = Nn - 1;
    const uint4* gAh = reinterpret_cast<const uint4*>(g_x + (size_t)arow * 512);
    const uint4* gAm = gAh + 32;    // +256 bf16 = +512 bytes = +32 uint4
    const uint4* gWh = reinterpret_cast<const uint4*>(g_wh + (size_t)lrow * 256);
    const uint4* gWm = reinterpret_cast<const uint4*>(g_wm + (size_t)lrow * 256);

    // plane order per buffer: Ah, Am, Wh, Wm
    auto issue = [&](int kc, int b) {
        #pragma unroll
        for (int t = 0; t < 2; t++) {
            int gi = kc * 4 + lt + t;
            uint32_t so = (uint32_t)(lrow * PITCH + (lt + t) * 8) * 2;
            uint32_t base = smem_b + (uint32_t)(b * 4) * PLANE_BYTES + so;
            CP16(base,                   gAh + gi);
            CP16(base + PLANE_BYTES,     gAm + gi);
            CP16(base + 2 * PLANE_BYTES, gWh + gi);
            CP16(base + 3 * PLANE_BYTES, gWm + gi);
        }
    };

    const int rA = (lane & 7) + ((lane >> 3) & 1) * 8;
    const int cA = (lane >> 4) * 8;
    const int rB = (lane & 7) + ((lane >> 4) & 1) * 8;
    const int cB = ((lane >> 3) & 1) * 8;

    issue(0, 0);
    CP_COMMIT();

    for (int kc = 0; kc < 8; kc++) {
        int b = kc & 1;
        if (kc < 7) {
            issue(kc + 1, b ^ 1);
            CP_COMMIT();
            CP_WAIT1();
        } else {
            CP_WAIT0();
        }
        __syncthreads();

        uint32_t pAh = smem_b + (uint32_t)(b * 4) * PLANE_BYTES;
        uint32_t pAm = pAh + PLANE_BYTES;
        uint32_t pWh = pAh + 2 * PLANE_BYTES;
        uint32_t pWm = pAh + 3 * PLANE_BYTES;

        #pragma unroll
        for (int kg = 0; kg < 2; kg++) {
            unsigned ah[2][4], am[2][4], bh[4][4], bm[4][4];
            #pragma unroll
            for (int mt = 0; mt < 2; mt++) {
                uint32_t a = pAh + (uint32_t)((warpM * 32 + mt * 16 + rA) * PITCH
                                              + kg * 16 + cA) * 2;
                LDMX4(ah[mt][0], ah[mt][1], ah[mt][2], ah[mt][3], a);
            }
            #pragma unroll
            for (int ng = 0; ng < 4; ng++) {
                uint32_t a = pWh + (uint32_t)((warpN * 64 + ng * 16 + rB) * PITCH
                                              + kg * 16 + cB) * 2;
                LDMX4(bh[ng][0], bh[ng][1], bh[ng][2], bh[ng][3], a);
            }
            #pragma unroll
            for (int mt = 0; mt < 2; mt++)
                #pragma unroll
                for (int ng = 0; ng < 4; ng++) {
                    MMA16816(d[mt][2 * ng],     ah[mt], bh[ng][0], bh[ng][1]);
                    MMA16816(d[mt][2 * ng + 1], ah[mt], bh[ng][2], bh[ng][3]);
                }
            #pragma unroll
            for (int ng = 0; ng < 4; ng++) {
                uint32_t a = pWm + (uint32_t)((warpN * 64 + ng * 16 + rB) * PITCH
                                              + kg * 16 + cB) * 2;
                LDMX4(bm[ng][0], bm[ng][1], bm[ng][2], bm[ng][3], a);
            }
            #pragma unroll
            for (int mt = 0; mt < 2; mt++)
                #pragma unroll
                for (int ng = 0; ng < 4; ng++) {
                    MMA16816(d[mt][2 * ng],     ah[mt], bm[ng][0], bm[ng][1]);
                    MMA16816(d[mt][2 * ng + 1], ah[mt], bm[ng][2], bm[ng][3]);
                }
            #pragma unroll
            for (int mt = 0; mt < 2; mt++) {
                uint32_t a = pAm + (uint32_t)((warpM * 32 + mt * 16 + rA) * PITCH
                                              + kg * 16 + cA) * 2;
                LDMX4(am[mt][0], am[mt][1], am[mt][2], am[mt][3], a);
            }
            #pragma unroll
            for (int mt = 0; mt < 2; mt++)
                #pragma unroll
                for (int ng = 0; ng < 4; ng++) {
                    MMA16816(d[mt][2 * ng],     am[mt], bh[ng][0], bh[ng][1]);
                    MMA16816(d[mt][2 * ng + 1], am[mt], bh[ng][2], bh[ng][3]);
                }
        }
        __syncthreads();
    }

    // epilogue
    const int l4 = lane >> 2;
    const int l2 = (lane & 3) * 2;
    #pragma unroll
    for (int mt = 0; mt < 2; mt++) {
        int m0 = mBase + warpM * 32 + mt * 16 + l4;
        int m1 = m0 + 8;
        bool v0 = (m0 < Nn), v1 = (m1 < Nn);
        float he0 = (v0 && g_counts[m0] > 0) ? 1.f : 0.f;
        float he1 = (v1 && g_counts[m1] > 0) ? 1.f : 0.f;
        #pragma unroll
        for (int nt = 0; nt < 8; nt++) {
            int col = warpN * 64 + nt * 8 + l2;
            float2 b2 = *reinterpret_cast<const float2*>(bn + col);
            float2 e2 = *reinterpret_cast<const float2*>(be + col);
            if (v0) {
                float2 o0 = make_float2(d[mt][nt][0] + b2.x + he0 * e2.x,
                                        d[mt][nt][1] + b2.y + he0 * e2.y);
                *reinterpret_cast<float2*>(out + (size_t)m0 * D + col) = o0;
            }
            if (v1) {
                float2 o1 = make_float2(d[mt][nt][2] + b2.x + he1 * e2.x,
                                        d[mt][nt][3] + b2.y + he1 * e2.y);
                *reinterpret_cast<float2*>(out + (size_t)m1 * D + col) = o1;
            }
        }
    }
}

// ---------------------------------------------------------------------------
extern "C" void kernel_launch(void* const* d_in, const int* in_sizes, int n_in,
                              void* d_out, int out_size)
{
    const float* nfeat = (const float*)d_in[0];
    const float* efeat = (const float*)d_in[1];
    const float* ew    = (const float*)d_in[2];
    const float* Wn    = (const float*)d_in[3];
    const float* bn    = (const float*)d_in[4];
    const float* We    = (const float*)d_in[5];
    const float* be    = (const float*)d_in[6];
    const int*   src   = (const int*)d_in[7];
    const int*   dst   = (const int*)d_in[8];
    float* out = (float*)d_out;

    int Nn = in_sizes[0] / D;     // 100000
    int E  = in_sizes[2];         // 1600000
    int nScanBlocks = (Nn + SCAN_B - 1) / SCAN_B;
    int zblocks = (Nn + 255) / 256;
    int cvblocks = (Nn * 32 + 255) / 256;     // float4 groups

    cudaFuncSetAttribute(gemm_mma, cudaFuncAttributeMaxDynamicSharedMemorySize,
                         GSMEM_TOTAL);

    prep_kernel<<<zblocks + 128 + cvblocks, 256>>>(Wn, We, nfeat, Nn, zblocks, cvblocks);
    hist_kernel<<<(E + 255) / 256, 256>>>(dst, E);
    scan1<<<nScanBlocks, SCAN_B>>>(Nn);
    scan_apply<<<nScanBlocks, SCAN_B>>>(Nn);
    scatter_ids<<<(E + 255) / 256, 256>>>(dst, src, ew, E);
    aggregate_kernel<<<(Nn + 7) / 8, 256>>>(nfeat, efeat, Nn);
    gemm_mma<<<(Nn + 127) / 128, 256, GSMEM_TOTAL>>>(bn, be, out, Nn);
}

// round 15
// speedup vs baseline: 1.5618x; 1.1407x over previous
#include <cuda_runtime.h>
#include <cuda_bf16.h>
#include <cuda_fp16.h>
#include <cstddef>
#include <cstdint>

#define D 128
#define NODES_CAP 100000
#define EDGES_CAP 1600000
#define SCAN_B 1024

// ---------------- scratch (__device__ globals; no allocation) ---------------
__device__ int   g_counts[NODES_CAP];
__device__ int   g_offs  [NODES_CAP];
__device__ int   g_bsum  [128];
__device__ int   g_scan_done;                      // zero-init; reset by last block
__device__ int4  g_swe   [EDGES_CAP];              // (src, ew bits, edge id, 0) sorted by dst
__device__ __half g_nf16[(size_t)NODES_CAP * 128]; // fp16 copy of nfeat (gather table)
__device__ __half g_x16 [(size_t)NODES_CAP * 256]; // fp16 X rows (256 = [xn 128 | xe 128])
__device__ __half g_wh16[128 * 256];               // Wcat hi  fp16 [o][k]
__device__ __half g_wm16[128 * 256];               // Wcat mid fp16 residual [o][k]

// ---------------------------------------------------------------------------
// prep: zero counts + weight split + nfeat->fp16 conversion, one launch
// ---------------------------------------------------------------------------
__global__ __launch_bounds__(256) void prep_kernel(
    const float* __restrict__ Wn, const float* __restrict__ We,
    const float* __restrict__ nfeat,
    int n_nodes, int zblocks)
{
    int b = blockIdx.x;
    if (b < zblocks) {
        int i = b * 256 + threadIdx.x;
        if (i < n_nodes) g_counts[i] = 0;
    } else if (b < zblocks + 128) {
        int i = (b - zblocks) * 256 + threadIdx.x;
        if (i < 128 * 256) {
            int o = i >> 8, k = i & 255;
            float w = (k < 128) ? Wn[o * 128 + k] : We[o * 128 + (k - 128)];
            __half h = __float2half_rn(w);
            g_wh16[i] = h;
            g_wm16[i] = __float2half_rn(w - __half2float(h));
        }
    } else {
        size_t i = (size_t)(b - zblocks - 128) * 256 + threadIdx.x;
        size_t total4 = (size_t)n_nodes * 32;
        if (i < total4) {
            float4 v = *(reinterpret_cast<const float4*>(nfeat) + i);
            __half2 h0 = __floats2half2_rn(v.x, v.y);
            __half2 h1 = __floats2half2_rn(v.z, v.w);
            uint2 p;
            p.x = *reinterpret_cast<unsigned*>(&h0);
            p.y = *reinterpret_cast<unsigned*>(&h1);
            reinterpret_cast<uint2*>(g_nf16)[i] = p;
        }
    }
}

__global__ __launch_bounds__(256) void hist_kernel(const int* __restrict__ dst, int E)
{
    int e = blockIdx.x * 256 + threadIdx.x;
    if (e < E) atomicAdd(&g_counts[dst[e]], 1);
}

// per-1024-block LOCAL exclusive scan into g_offs; block totals into g_bsum.
// Last block (ticket pattern) scans g_bsum exclusive in place.
__global__ __launch_bounds__(SCAN_B) void scan1(int n)
{
    __shared__ int wsum[32];
    __shared__ int ws2[4];
    __shared__ int s_ticket;
    int tid = threadIdx.x;
    int i = blockIdx.x * SCAN_B + tid;
    int v = (i < n) ? g_counts[i] : 0;
    int x = v;
    #pragma unroll
    for (int d = 1; d < 32; d <<= 1) {
        int y = __shfl_up_sync(0xffffffffu, x, d);
        if ((tid & 31) >= d) x += y;
    }
    if ((tid & 31) == 31) wsum[tid >> 5] = x;
    __syncthreads();
    if (tid < 32) {
        int y = wsum[tid];
        #pragma unroll
        for (int d = 1; d < 32; d <<= 1) {
            int z = __shfl_up_sync(0xffffffffu, y, d);
            if (tid >= d) y += z;
        }
        wsum[tid] = y;
    }
    __syncthreads();
    int base = (tid >= 32) ? wsum[(tid >> 5) - 1] : 0;
    int incl = base + x;
    if (i < n) g_offs[i] = incl - v;                 // LOCAL exclusive start
    if (tid == SCAN_B - 1) g_bsum[blockIdx.x] = incl;

    // last block scans g_bsum exclusive in place
    __threadfence();
    if (tid == 0) s_ticket = atomicAdd(&g_scan_done, 1);
    __syncthreads();
    if (s_ticket == (int)gridDim.x - 1) {
        int nb = gridDim.x;
        int bv = 0, bx = 0;
        if (tid < 128) {
            bv = (tid < nb) ? g_bsum[tid] : 0;
            bx = bv;
            #pragma unroll
            for (int d = 1; d < 32; d <<= 1) {
                int z = __shfl_up_sync(0xffffffffu, bx, d);
                if ((tid & 31) >= d) bx += z;
            }
            if ((tid & 31) == 31) ws2[tid >> 5] = bx;
        }
        __syncthreads();
        if (tid == 0) {
            int r = 0;
            #pragma unroll
            for (int j = 0; j < 4; j++) { int t = ws2[j]; ws2[j] = r; r += t; }
        }
        __syncthreads();
        if (tid < nb) g_bsum[tid] = bx - bv + ws2[tid >> 5];   // exclusive
        if (tid == 0) g_scan_done = 0;
    }
}

__global__ __launch_bounds__(256) void scatter_ids(
    const int* __restrict__ dst, const int* __restrict__ src,
    const float* __restrict__ ew, int E)
{
    int e = blockIdx.x * 256 + threadIdx.x;
    if (e < E) {
        int d = dst[e];
        int p = atomicAdd(&g_offs[d], 1) + __ldg(&g_bsum[d >> 10]);
        g_swe[p] = make_int4(src[e], __float_as_int(ew[e]), e, 0);
    }
}

// ---------------------------------------------------------------------------
// Warp-per-node aggregation; fp16 gather; writes fp16 X row (256 fp16, 512B).
// ---------------------------------------------------------------------------
__device__ __forceinline__ float4 gather_h4(const uint2* row, int lane)
{
    uint2 p = __ldg(row + lane);
    __half2 h0 = *reinterpret_cast<__half2*>(&p.x);
    __half2 h1 = *reinterpret_cast<__half2*>(&p.y);
    float2 f0 = __half22float2(h0);
    float2 f1 = __half22float2(h1);
    return make_float4(f0.x, f0.y, f1.x, f1.y);
}
__device__ __forceinline__ uint2 packh4(float4 v)
{
    __half2 h0 = __floats2half2_rn(v.x, v.y);
    __half2 h1 = __floats2half2_rn(v.z, v.w);
    uint2 r;
    r.x = *reinterpret_cast<unsigned*>(&h0);
    r.y = *reinterpret_cast<unsigned*>(&h1);
    return r;
}

__global__ __launch_bounds__(256) void aggregate_kernel(
    const float* __restrict__ nfeat, const float* __restrict__ efeat, int Nn)
{
    int n = blockIdx.x * 8 + (threadIdx.x >> 5);
    if (n >= Nn) return;
    int lane = threadIdx.x & 31;

    int cnt = g_counts[n];
    int end = g_offs[n] + __ldg(&g_bsum[n >> 10]);   // global end
    int beg = end - cnt;

    const float4* nf4 = reinterpret_cast<const float4*>(nfeat);
    const float4* ef4 = reinterpret_cast<const float4*>(efeat);
    const uint2*  nh  = reinterpret_cast<const uint2*>(g_nf16);

    float4 aN = make_float4(0.f, 0.f, 0.f, 0.f);
    float4 aE = make_float4(0.f, 0.f, 0.f, 0.f);

    int i = beg;
    for (; i + 4 <= end; i += 4) {
        int4 q0 = __ldcs(g_swe + i);
        int4 q1 = __ldcs(g_swe + i + 1);
        int4 q2 = __ldcs(g_swe + i + 2);
        int4 q3 = __ldcs(g_swe + i + 3);
        float4 a0 = gather_h4(nh + (size_t)q0.x * 32, lane);
        float4 a1 = gather_h4(nh + (size_t)q1.x * 32, lane);
        float4 a2 = gather_h4(nh + (size_t)q2.x * 32, lane);
        float4 a3 = gather_h4(nh + (size_t)q3.x * 32, lane);
        float4 v0 = __ldcs(ef4 + (size_t)q0.z * 32 + lane);
        float4 v1 = __ldcs(ef4 + (size_t)q1.z * 32 + lane);
        float4 v2 = __ldcs(ef4 + (size_t)q2.z * 32 + lane);
        float4 v3 = __ldcs(ef4 + (size_t)q3.z * 32 + lane);
        float w0 = __int_as_float(q0.y), w1 = __int_as_float(q1.y);
        float w2 = __int_as_float(q2.y), w3 = __int_as_float(q3.y);
        aN.x += a0.x * w0 + a1.x * w1 + a2.x * w2 + a3.x * w3;
        aN.y += a0.y * w0 + a1.y * w1 + a2.y * w2 + a3.y * w3;
        aN.z += a0.z * w0 + a1.z * w1 + a2.z * w2 + a3.z * w3;
        aN.w += a0.w * w0 + a1.w * w1 + a2.w * w2 + a3.w * w3;
        aE.x += (v0.x + v1.x) + (v2.x + v3.x);
        aE.y += (v0.y + v1.y) + (v2.y + v3.y);
        aE.z += (v0.z + v1.z) + (v2.z + v3.z);
        aE.w += (v0.w + v1.w) + (v2.w + v3.w);
    }
    for (; i < end; i++) {
        int4 q = __ldcs(g_swe + i);
        float w = __int_as_float(q.y);
        float4 a = gather_h4(nh + (size_t)q.x * 32, lane);
        float4 v = __ldcs(ef4 + (size_t)q.z * 32 + lane);
        aN.x += a.x * w;  aN.y += a.y * w;  aN.z += a.z * w;  aN.w += a.w * w;
        aE.x += v.x;  aE.y += v.y;  aE.z += v.z;  aE.w += v.w;
    }

    float invD = 1.f / ((float)cnt + 1.f);
    float invE = 1.f / (float)max(cnt, 1);
    float4 f = __ldg(nf4 + (size_t)n * 32 + lane);   // self term fp32

    float4 xn = make_float4((aN.x + 2.f * f.x) * invD, (aN.y + 2.f * f.y) * invD,
                            (aN.z + 2.f * f.z) * invD, (aN.w + 2.f * f.w) * invD);
    float4 xe = make_float4(aE.x * invE, aE.y * invE, aE.z * invE, aE.w * invE);

    uint2* xr = reinterpret_cast<uint2*>(g_x16 + (size_t)n * 256);
    xr[lane]      = packh4(xn);
    xr[32 + lane] = packh4(xe);
}

// ---------------------------------------------------------------------------
// fp16 HMMA GEMM, 2 passes (A*Wh + A*Wm), cp.async double-buffered.
// Block: 128(M) x 128(N), 8 warps (4Mx2N), warp tile 32x64, K in 8 chunks of 32.
// Smem pitch 40 fp16, 3 planes (A, Wh, Wm) x 2 buffers = 60KB.
// ---------------------------------------------------------------------------
#define LDMX4(r0, r1, r2, r3, addr)                                                \
    asm volatile("ldmatrix.sync.aligned.m8n8.x4.shared.b16 {%0,%1,%2,%3}, [%4];"   \
                 : "=r"(r0), "=r"(r1), "=r"(r2), "=r"(r3) : "r"(addr))

#define MMAF16(d, a, b0, b1)                                                       \
    asm volatile("mma.sync.aligned.m16n8k16.row.col.f32.f16.f16.f32 "              \
                 "{%0,%1,%2,%3},{%4,%5,%6,%7},{%8,%9},{%0,%1,%2,%3};"              \
                 : "+f"((d)[0]), "+f"((d)[1]), "+f"((d)[2]), "+f"((d)[3])          \
                 : "r"((a)[0]), "r"((a)[1]), "r"((a)[2]), "r"((a)[3]),             \
                   "r"(b0), "r"(b1))

#define CP16(dst, src)                                                             \
    asm volatile("cp.async.cg.shared.global [%0], [%1], 16;" :: "r"(dst), "l"(src))
#define CP_COMMIT() asm volatile("cp.async.commit_group;" ::: "memory")
#define CP_WAIT1()  asm volatile("cp.async.wait_group 1;" ::: "memory")
#define CP_WAIT0()  asm volatile("cp.async.wait_group 0;" ::: "memory")

#define PITCH 40
#define PLANE_ELEMS (128 * PITCH)
#define PLANE_BYTES (PLANE_ELEMS * 2)
#define GSMEM_TOTAL (6 * PLANE_BYTES)     // 61440

__global__ __launch_bounds__(256) void gemm_mma(
    const float* __restrict__ bn, const float* __restrict__ be,
    float* __restrict__ out, int Nn)
{
    extern __shared__ __half smem[];
    const uint32_t smem_b = (uint32_t)__cvta_generic_to_shared(smem);

    const int tid  = threadIdx.x;
    const int wid  = tid >> 5;
    const int lane = tid & 31;
    const int warpM = wid & 3;
    const int warpN = wid >> 2;
    const int mBase = blockIdx.x * 128;

    float d[2][8][4];
    #pragma unroll
    for (int mt = 0; mt < 2; mt++)
        #pragma unroll
        for (int nt = 0; nt < 8; nt++)
            #pragma unroll
            for (int c = 0; c < 4; c++) d[mt][nt][c] = 0.f;

    // loaders: 2 threads per row, each 2 x 16B of the 64B k-chunk row
    const int lrow = tid >> 1;
    const int lt   = (tid & 1) * 2;
    int arow = mBase + lrow; if (arow >= Nn) arow = Nn - 1;
    const uint4* gA  = reinterpret_cast<const uint4*>(g_x16 + (size_t)arow * 256);
    const uint4* gWh = reinterpret_cast<const uint4*>(g_wh16 + (size_t)lrow * 256);
    const uint4* gWm = reinterpret_cast<const uint4*>(g_wm16 + (size_t)lrow * 256);

    // planes per buffer: A, Wh, Wm
    auto issue = [&](int kc, int b) {
        #pragma unroll
        for (int t = 0; t < 2; t++) {
            int gi = kc * 4 + lt + t;
            uint32_t so = (uint32_t)(lrow * PITCH + (lt + t) * 8) * 2;
            uint32_t base = smem_b + (uint32_t)(b * 3) * PLANE_BYTES + so;
            CP16(base,                   gA  + gi);
            CP16(base + PLANE_BYTES,     gWh + gi);
            CP16(base + 2 * PLANE_BYTES, gWm + gi);
        }
    };

    const int rA = (lane & 7) + ((lane >> 3) & 1) * 8;
    const int cA = (lane >> 4) * 8;
    const int rB = (lane & 7) + ((lane >> 4) & 1) * 8;
    const int cB = ((lane >> 3) & 1) * 8;

    issue(0, 0);
    CP_COMMIT();

    for (int kc = 0; kc < 8; kc++) {
        int b = kc & 1;
        if (kc < 7) {
            issue(kc + 1, b ^ 1);
            CP_COMMIT();
            CP_WAIT1();
        } else {
            CP_WAIT0();
        }
        __syncthreads();

        uint32_t pA  = smem_b + (uint32_t)(b * 3) * PLANE_BYTES;
        uint32_t pWh = pA + PLANE_BYTES;
        uint32_t pWm = pA + 2 * PLANE_BYTES;

        #pragma unroll
        for (int kg = 0; kg < 2; kg++) {
            unsigned ah[2][4], bh[4][4], bm[4][4];
            #pragma unroll
            for (int mt = 0; mt < 2; mt++) {
                uint32_t a = pA + (uint32_t)((warpM * 32 + mt * 16 + rA) * PITCH
                                             + kg * 16 + cA) * 2;
                LDMX4(ah[mt][0], ah[mt][1], ah[mt][2], ah[mt][3], a);
            }
            #pragma unroll
            for (int ng = 0; ng < 4; ng++) {
                uint32_t a = pWh + (uint32_t)((warpN * 64 + ng * 16 + rB) * PITCH
                                              + kg * 16 + cB) * 2;
                LDMX4(bh[ng][0], bh[ng][1], bh[ng][2], bh[ng][3], a);
            }
            #pragma unroll
            for (int mt = 0; mt < 2; mt++)
                #pragma unroll
                for (int ng = 0; ng < 4; ng++) {
                    MMAF16(d[mt][2 * ng],     ah[mt], bh[ng][0], bh[ng][1]);
                    MMAF16(d[mt][2 * ng + 1], ah[mt], bh[ng][2], bh[ng][3]);
                }
            #pragma unroll
            for (int ng = 0; ng < 4; ng++) {
                uint32_t a = pWm + (uint32_t)((warpN * 64 + ng * 16 + rB) * PITCH
                                              + kg * 16 + cB) * 2;
                LDMX4(bm[ng][0], bm[ng][1], bm[ng][2], bm[ng][3], a);
            }
            #pragma unroll
            for (int mt = 0; mt < 2; mt++)
                #pragma unroll
                for (int ng = 0; ng < 4; ng++) {
                    MMAF16(d[mt][2 * ng],     ah[mt], bm[ng][0], bm[ng][1]);
                    MMAF16(d[mt][2 * ng + 1], ah[mt], bm[ng][2], bm[ng][3]);
                }
        }
        __syncthreads();
    }

    // epilogue
    const int l4 = lane >> 2;
    const int l2 = (lane & 3) * 2;
    #pragma unroll
    for (int mt = 0; mt < 2; mt++) {
        int m0 = mBase + warpM * 32 + mt * 16 + l4;
        int m1 = m0 + 8;
        bool v0 = (m0 < Nn), v1 = (m1 < Nn);
        float he0 = (v0 && g_counts[m0] > 0) ? 1.f : 0.f;
        float he1 = (v1 && g_counts[m1] > 0) ? 1.f : 0.f;
        #pragma unroll
        for (int nt = 0; nt < 8; nt++) {
            int col = warpN * 64 + nt * 8 + l2;
            float2 b2 = *reinterpret_cast<const float2*>(bn + col);
            float2 e2 = *reinterpret_cast<const float2*>(be + col);
            if (v0) {
                float2 o0 = make_float2(d[mt][nt][0] + b2.x + he0 * e2.x,
                                        d[mt][nt][1] + b2.y + he0 * e2.y);
                *reinterpret_cast<float2*>(out + (size_t)m0 * D + col) = o0;
            }
            if (v1) {
                float2 o1 = make_float2(d[mt][nt][2] + b2.x + he1 * e2.x,
                                        d[mt][nt][3] + b2.y + he1 * e2.y);
                *reinterpret_cast<float2*>(out + (size_t)m1 * D + col) = o1;
            }
        }
    }
}

// ---------------------------------------------------------------------------
extern "C" void kernel_launch(void* const* d_in, const int* in_sizes, int n_in,
                              void* d_out, int out_size)
{
    const float* nfeat = (const float*)d_in[0];
    const float* efeat = (const float*)d_in[1];
    const float* ew    = (const float*)d_in[2];
    const float* Wn    = (const float*)d_in[3];
    const float* bn    = (const float*)d_in[4];
    const float* We    = (const float*)d_in[5];
    const float* be    = (const float*)d_in[6];
    const int*   src   = (const int*)d_in[7];
    const int*   dst   = (const int*)d_in[8];
    float* out = (float*)d_out;

    int Nn = in_sizes[0] / D;     // 100000
    int E  = in_sizes[2];         // 1600000
    int nScanBlocks = (Nn + SCAN_B - 1) / SCAN_B;
    int zblocks = (Nn + 255) / 256;
    int cvblocks = (Nn * 32 + 255) / 256;

    cudaFuncSetAttribute(gemm_mma, cudaFuncAttributeMaxDynamicSharedMemorySize,
                         GSMEM_TOTAL);

    prep_kernel<<<zblocks + 128 + cvblocks, 256>>>(Wn, We, nfeat, Nn, zblocks);
    hist_kernel<<<(E + 255) / 256, 256>>>(dst, E);
    scan1<<<nScanBlocks, SCAN_B>>>(Nn);
    scatter_ids<<<(E + 255) / 256, 256>>>(dst, src, ew, E);
    aggregate_kernel<<<(Nn + 7) / 8, 256>>>(nfeat, efeat, Nn);
    gemm_mma<<<(Nn + 127) / 128, 256, GSMEM_TOTAL>>>(bn, be, out, Nn);
}